// round 12
// baseline (speedup 1.0000x reference)
#include <cuda_runtime.h>
#include <cuda_fp16.h>
#include <cstdint>

#define BB   64
#define SS   1024
#define EE   128
#define HH   512
#define GG   2048
#define NTHR 256
#define NCR  64        // rnn CTAs
#define HPC  8         // h columns per CTA
#define MRR  32        // D rows per CTA = 4 gates x 8 h

// ---- rnn dynamic smem layout (bytes) ----
#define A_BYTES  (MRR * HH * 2)          // 32768 fp16 Wh tile (1024B rows, swizzled)
#define B_BYTES  (BB * HH * 2)           // 65536 fp16 H tile (1024B rows, swizzled)
#define WX_OFF   (A_BYTES + B_BYTES)     // 98304: Wx tile [32 m][128 k] fp16, 256B rows
#define WX_BYTES (MRR * EE * 2)          // 8192
#define XS_OFF   (WX_OFF + WX_BYTES)     // 106496: X tile [64 b][128 k] fp16, 256B rows
#define XS_BYTES (BB * EE * 2)           // 16384
#define G_OFF    (XS_OFF + XS_BYTES)     // 122880: Gsm float[32][72]
#define G_BYTES  (MRR * 72 * 4)          // 9216
#define HN_OFF   (G_OFF + G_BYTES)       // 132096: HnSm half[8][66]
#define HN_BYTES (8 * 66 * 2)            // 1056
#define YS_OFF   (HN_OFF + HN_BYTES + 8) // 133160 -> align16 -> use 133168
#define YS_OFF2  ((HN_OFF + HN_BYTES + 15) & ~15)
#define YS_BYTES (8 * 72 * 4)            // 2304
#define RNN_SMEM (YS_OFF2 + YS_BYTES)    // ~135472

// ---------------- module-scope scratch ----------------
__device__ __align__(128) __half        g_Hbuf[2][BB * HH];           // [b][h] fp16
__device__ __align__(128) float         g_Cbuf[HH * BB];              // [h][b]
__device__ __align__(128) float         g_Hfin[HH * BB];              // [h][b]
__device__ __align__(128) float         g_weff[HH];
__device__ __align__(128) float         g_beff[1];
__device__ __align__(128) float         g_party[(size_t)NCR * SS * BB];
__device__ __align__(128) unsigned      g_bar[SS];                    // step arrival counters
__device__ __align__(128) unsigned char g_Abuf[(size_t)NCR * A_BYTES];   // Wh images
__device__ __align__(128) unsigned char g_Wxbuf[(size_t)NCR * WX_BYTES]; // Wx images

__device__ __forceinline__ float sigf(float x)   { return 1.f / (1.f + __expf(-x)); }
__device__ __forceinline__ float tanhf_(float x) { return 2.f / (1.f + __expf(-2.f * x)) - 1.f; }

__device__ __forceinline__ uint32_t smem_u32(const void* p) {
    uint32_t a;
    asm("{ .reg .u64 t; cvta.to.shared.u64 t, %1; cvt.u32.u64 %0, t; }" : "=r"(a) : "l"(p));
    return a;
}
__device__ __forceinline__ void ldsm4(uint32_t* r, uint32_t addr) {
    asm volatile("ldmatrix.sync.aligned.m8n8.x4.shared.b16 {%0,%1,%2,%3}, [%4];"
                 : "=r"(r[0]), "=r"(r[1]), "=r"(r[2]), "=r"(r[3]) : "r"(addr));
}
__device__ __forceinline__ void mma16816(float* d, const uint32_t* a, const uint32_t* b) {
    asm volatile("mma.sync.aligned.m16n8k16.row.col.f32.f16.f16.f32 "
                 "{%0,%1,%2,%3}, {%4,%5,%6,%7}, {%8,%9}, {%0,%1,%2,%3};"
                 : "+f"(d[0]), "+f"(d[1]), "+f"(d[2]), "+f"(d[3])
                 : "r"(a[0]), "r"(a[1]), "r"(a[2]), "r"(a[3]), "r"(b[0]), "r"(b[1]));
}

// ---------------- init ----------------
__global__ void __launch_bounds__(NTHR) init_kernel(
    const float* __restrict__ H0, const float* __restrict__ C0,
    const float* __restrict__ Whq, const float* __restrict__ bq,
    const float* __restrict__ dw, const float* __restrict__ db)
{
    int t = blockIdx.x * blockDim.x + threadIdx.x;
    if (t < HH * BB) {
        int b = t >> 9, h = t & 511;
        g_Hbuf[0][t]       = __float2half_rn(H0[t]);   // [b][h]
        g_Cbuf[h * BB + b] = C0[t];
    }
    if (t < HH) {
        float a = 0.f;
        #pragma unroll 8
        for (int e = 0; e < EE; e++) a += Whq[t * EE + e] * dw[e];
        g_weff[t] = a;
    }
    if (t == 0) {
        float a = 0.f;
        for (int e = 0; e < EE; e++) a += bq[e] * dw[e];
        g_beff[0] = a + db[0];
    }
    if (t < SS) g_bar[t] = 0u;
}

// ---------------- prep: Wh images (1024B rows, swizzled fp16) ----------------
__global__ void __launch_bounds__(NTHR) prep_kernel(
    const float* __restrict__ Whi, const float* __restrict__ Whf,
    const float* __restrict__ Who, const float* __restrict__ Whc)
{
    int idx = blockIdx.x * blockDim.x + threadIdx.x;   // 64*32*512 = 1M
    int c = idx >> 14;
    int r = idx & 16383;
    int m = r >> 9;
    int k = r & 511;
    int g = m >> 3, u = m & 7;
    const float* W = (g == 0) ? Whi : (g == 1) ? Whf : (g == 2) ? Who : Whc;
    float v = W[(size_t)k * HH + c * HPC + u];
    uint32_t pos = (uint32_t)m * 1024 + (((uint32_t)k * 2) ^ (((uint32_t)m & 7) << 4));
    *(__half*)(g_Abuf + (size_t)c * A_BYTES + pos) = __float2half_rn(v);
}

// ---------------- prep_x: Wx images (256B rows, swizzled fp16) ---------------
// For CTA c: row m = g*8+u (m 0..31), k 0..127, value Wx_g[k][c*8+u]
__global__ void __launch_bounds__(NTHR) prep_x_kernel(
    const float* __restrict__ Wxi, const float* __restrict__ Wxf,
    const float* __restrict__ Wxo, const float* __restrict__ Wxc)
{
    int idx = blockIdx.x * blockDim.x + threadIdx.x;   // 64*32*128 = 262144
    int c = idx >> 12;
    int r = idx & 4095;
    int m = r >> 7;
    int k = r & 127;
    int g = m >> 3, u = m & 7;
    const float* W = (g == 0) ? Wxi : (g == 1) ? Wxf : (g == 2) ? Wxo : Wxc;
    float v = W[(size_t)k * HH + c * HPC + u];
    uint32_t pos = (uint32_t)m * 256 + (((uint32_t)k * 2) ^ (((uint32_t)m & 7) << 4));
    *(__half*)(g_Wxbuf + (size_t)c * WX_BYTES + pos) = __float2half_rn(v);
}

// ---------------- persistent recurrence, fused x-gate GEMM, 64 CTAs ----------
__global__ void __launch_bounds__(NTHR, 1) rnn_kernel(
    const int* __restrict__ inputs, const float* __restrict__ emb,
    const float* __restrict__ bi,  const float* __restrict__ bf,
    const float* __restrict__ bo,  const float* __restrict__ bc)
{
    extern __shared__ __align__(16) unsigned char sm[];
    float*  Gsm  = (float*)(sm + G_OFF);
    __half* HnSm = (__half*)(sm + HN_OFF);
    float*  Ysm  = (float*)(sm + YS_OFF2);
    const uint32_t smb = smem_u32(sm);
    const uint32_t Ab  = smb;
    const uint32_t Bb  = smb + A_BYTES;
    const uint32_t WxB = smb + WX_OFF;
    const uint32_t XsB = smb + XS_OFF;

    const int t = threadIdx.x, lane = t & 31, wid = t >> 5;
    const int cta = blockIdx.x, hbase = cta * HPC;

    // load prebuilt Wh image (32 KB) + Wx image (8 KB)
    {
        const float4* asrc = (const float4*)(g_Abuf + (size_t)cta * A_BYTES);
        float4* adst = (float4*)sm;
        #pragma unroll
        for (int j = 0; j < 8; j++)
            adst[j * 256 + t] = __ldg(&asrc[j * 256 + t]);
        const float4* xsrc = (const float4*)(g_Wxbuf + (size_t)cta * WX_BYTES);
        float4* xdst = (float4*)(sm + WX_OFF);
        if (t < 128) {
            xdst[t]       = __ldg(&xsrc[t]);
            xdst[t + 128] = __ldg(&xsrc[t + 128]);
            xdst[t + 256] = __ldg(&xsrc[t + 256]);
            xdst[t + 384] = __ldg(&xsrc[t + 384]);
        }
    }

    // ldmatrix lane-address precompute (proven pattern)
    const int q = lane >> 3, r8 = lane & 7;
    const int mt = wid & 1;
    const int np = wid >> 1;
    const int arow = mt * 16 + r8 + ((q & 1) << 3);
    const uint32_t acol = (uint32_t)(q >> 1) * 16;
    const uint32_t aBase = Ab + (uint32_t)arow * 1024;
    const uint32_t axor  = ((uint32_t)arow & 7) << 4;
    const int brow = np * 16 + r8 + ((q >> 1) << 3);
    const uint32_t bcol = (uint32_t)(q & 1) * 16;
    const uint32_t bBase = Bb + (uint32_t)brow * 1024;
    const uint32_t bxor  = ((uint32_t)brow & 7) << 4;
    // X-GEMM bases: same lane mapping, 256B rows
    const uint32_t aBaseX = WxB + (uint32_t)arow * 256;
    const uint32_t bBaseX = XsB + (uint32_t)brow * 256;

    // epilogue role
    const int u = wid, eb = lane;
    float C0r = g_Cbuf[(hbase + u) * BB + eb];
    float C1r = g_Cbuf[(hbase + u) * BB + eb + 32];
    const float wef  = g_weff[hbase + u];
    const float bi_r = __ldg(&bi[hbase + u]);
    const float bf_r = __ldg(&bf[hbase + u]);
    const float bo_r = __ldg(&bo[hbase + u]);
    const float bc_r = __ldg(&bc[hbase + u]);
    __syncthreads();

    // X-gather role (constant across steps)
    const int bqi = t >> 2, part = t & 3;
    const int* tok_ptr = inputs + bqi * SS;   // + s each step

    for (int step = 0; step < SS; step++) {
        // stage H [b][h] fp16 -> Bsm, per-row XOR swizzle (R10-exact)
        {
            const float4* hs = (const float4*)g_Hbuf[step & 1];
            #pragma unroll
            for (int j = 0; j < 16; j++) {
                int i16 = j * 256 + t;
                float4 v = __ldcg(&hs[i16]);
                uint32_t b   = (uint32_t)i16 >> 6;
                uint32_t c16 = (uint32_t)i16 & 63;
                *(float4*)(sm + A_BYTES + b * 1024 + ((c16 * 16) ^ ((b & 7) << 4))) = v;
            }
        }
        // stage X: emb[tok] fp32 -> fp16, 256B swizzled rows
        {
            int tok = __ldg(tok_ptr + step);
            const float4* src = (const float4*)(emb + (size_t)tok * EE) + part * 8;
            #pragma unroll
            for (int i = 0; i < 4; i++) {
                float4 v0 = __ldg(&src[i * 2]);
                float4 v1 = __ldg(&src[i * 2 + 1]);
                __half2 h0 = __floats2half2_rn(v0.x, v0.y);
                __half2 h1 = __floats2half2_rn(v0.z, v0.w);
                __half2 h2 = __floats2half2_rn(v1.x, v1.y);
                __half2 h3 = __floats2half2_rn(v1.z, v1.w);
                uint4 uu = make_uint4(*(uint32_t*)&h0, *(uint32_t*)&h1,
                                      *(uint32_t*)&h2, *(uint32_t*)&h3);
                uint32_t col = (uint32_t)part * 64 + (uint32_t)i * 16;
                *(uint4*)(sm + XS_OFF + bqi * 256 + (col ^ (((uint32_t)bqi & 7) << 4))) = uu;
            }
        }
        __syncthreads();

        // GEMM: 8 X k-slices (K=128) + 32 H k-slices (K=512), same accumulators
        float d0[4] = {0.f, 0.f, 0.f, 0.f};
        float d1[4] = {0.f, 0.f, 0.f, 0.f};
        #pragma unroll
        for (int ks = 0; ks < 8; ks++) {
            uint32_t a[4], b2[4];
            ldsm4(a,  aBaseX + (((uint32_t)ks * 32 + acol) ^ axor));
            ldsm4(b2, bBaseX + (((uint32_t)ks * 32 + bcol) ^ bxor));
            mma16816(d0, a, b2);
            mma16816(d1, a, b2 + 2);
        }
        #pragma unroll 8
        for (int ks = 0; ks < 32; ks++) {
            uint32_t a[4], b2[4];
            ldsm4(a,  aBase + (((uint32_t)ks * 32 + acol) ^ axor));
            ldsm4(b2, bBase + (((uint32_t)ks * 32 + bcol) ^ bxor));
            mma16816(d0, a, b2);
            mma16816(d1, a, b2 + 2);
        }
        {
            int g4 = lane >> 2, t4 = lane & 3;
            int mrow = mt * 16 + g4, nc = np * 16 + 2 * t4;
            *(float2*)&Gsm[mrow * 72 + nc]           = make_float2(d0[0], d0[1]);
            *(float2*)&Gsm[(mrow + 8) * 72 + nc]     = make_float2(d0[2], d0[3]);
            *(float2*)&Gsm[mrow * 72 + nc + 8]       = make_float2(d1[0], d1[1]);
            *(float2*)&Gsm[(mrow + 8) * 72 + nc + 8] = make_float2(d1[2], d1[3]);
        }
        __syncthreads();

        // epilogue: 2 cells per thread (bias from registers)
        {
            float pi = bi_r + Gsm[( 0 + u) * 72 + eb];
            float pf = bf_r + Gsm[( 8 + u) * 72 + eb];
            float po = bo_r + Gsm[(16 + u) * 72 + eb];
            float pc = bc_r + Gsm[(24 + u) * 72 + eb];
            float I = sigf(pi), F = sigf(pf), O = sigf(po), Ct = tanhf_(pc);
            C0r = F * C0r + I * Ct;
            float Hn = O * tanhf_(C0r);
            HnSm[u * 66 + eb] = __float2half_rn(Hn);
            Ysm[u * 72 + eb]  = Hn * wef;
            if (step == SS - 1) { g_Hfin[(hbase + u) * BB + eb] = Hn; g_Cbuf[(hbase + u) * BB + eb] = C0r; }
        }
        {
            int bb = eb + 32;
            float pi = bi_r + Gsm[( 0 + u) * 72 + bb];
            float pf = bf_r + Gsm[( 8 + u) * 72 + bb];
            float po = bo_r + Gsm[(16 + u) * 72 + bb];
            float pc = bc_r + Gsm[(24 + u) * 72 + bb];
            float I = sigf(pi), F = sigf(pf), O = sigf(po), Ct = tanhf_(pc);
            C1r = F * C1r + I * Ct;
            float Hn = O * tanhf_(C1r);
            HnSm[u * 66 + bb] = __float2half_rn(Hn);
            Ysm[u * 72 + bb]  = Hn * wef;
            if (step == SS - 1) { g_Hfin[(hbase + u) * BB + bb] = Hn; g_Cbuf[(hbase + u) * BB + bb] = C1r; }
        }
        __syncthreads();

        // pack new H (coalesced 16B per batch) + Y partial
        if (t < BB) {
            uint32_t p[4];
            #pragma unroll
            for (int uu = 0; uu < 4; uu++) {
                uint32_t lo = (uint32_t)__half_as_ushort(HnSm[(2 * uu)     * 66 + t]);
                uint32_t hi = (uint32_t)__half_as_ushort(HnSm[(2 * uu + 1) * 66 + t]);
                p[uu] = lo | (hi << 16);
            }
            *(uint4*)((unsigned char*)g_Hbuf[(step + 1) & 1] + (size_t)t * 1024 + (size_t)cta * 16)
                = make_uint4(p[0], p[1], p[2], p[3]);
        } else if (t < 2 * BB) {
            int bb = t - BB;
            float y = 0.f;
            #pragma unroll
            for (int uu = 0; uu < 8; uu++) y += Ysm[uu * 72 + bb];
            g_party[((size_t)cta * SS + step) * BB + bb] = y;
        }

        // ---- R5-proven 64-CTA barrier: atomic arrival + atomic poll ----
        __threadfence();
        __syncthreads();
        if (t == 0) {
            atomicAdd(&g_bar[step], 1u);
            while (atomicAdd(&g_bar[step], 0u) < (unsigned)NCR) { }
            __threadfence();
        }
        __syncthreads();
    }
}

// ---------------- finalize ----------------------------------------------------
__global__ void __launch_bounds__(NTHR) fin_kernel(float* __restrict__ out, int out_size)
{
    int blk = blockIdx.x, t = threadIdx.x;
    if (blk < SS) {
        if (t < BB) {
            float y = g_beff[0];
            #pragma unroll
            for (int c = 0; c < NCR; c++)
                y += g_party[((size_t)c * SS + blk) * BB + t];
            int o = blk * BB + t;
            if (o < out_size) out[o] = y;
        }
    } else {
        if (out_size < SS * BB + 2 * HH * BB) return;
        int i = (blk - SS) * NTHR + t;
        if (i < HH * BB) {
            int h = i >> 6, b = i & 63;
            out[SS * BB + b * HH + h] = g_Hfin[i];
        } else {
            int j = i - HH * BB;
            int h = j >> 6, b = j & 63;
            out[SS * BB + HH * BB + b * HH + h] = g_Cbuf[j];
        }
    }
}

// ---------------- launch ------------------------------------------------------
extern "C" void kernel_launch(void* const* d_in, const int* in_sizes, int n_in,
                              void* d_out, int out_size)
{
    const int*   inputs = (const int*)d_in[0];
    const float* H0  = (const float*)d_in[1];
    const float* C0  = (const float*)d_in[2];
    const float* emb = (const float*)d_in[3];
    const float* Wxi = (const float*)d_in[4];
    const float* Whi = (const float*)d_in[5];
    const float* bi  = (const float*)d_in[6];
    const float* Wxf = (const float*)d_in[7];
    const float* Whf = (const float*)d_in[8];
    const float* bf  = (const float*)d_in[9];
    const float* Wxo = (const float*)d_in[10];
    const float* Who = (const float*)d_in[11];
    const float* bo  = (const float*)d_in[12];
    const float* Wxc = (const float*)d_in[13];
    const float* Whc = (const float*)d_in[14];
    const float* bc  = (const float*)d_in[15];
    const float* Whq = (const float*)d_in[16];
    const float* bq  = (const float*)d_in[17];
    const float* dw  = (const float*)d_in[18];
    const float* db  = (const float*)d_in[19];
    float* out = (float*)d_out;

    cudaFuncSetAttribute(rnn_kernel, cudaFuncAttributeMaxDynamicSharedMemorySize, RNN_SMEM);

    init_kernel<<<128, NTHR>>>(H0, C0, Whq, bq, dw, db);
    prep_kernel<<<(NCR * MRR * HH) / NTHR, NTHR>>>(Whi, Whf, Who, Whc);
    prep_x_kernel<<<(NCR * MRR * EE) / NTHR, NTHR>>>(Wxi, Wxf, Wxo, Wxc);
    rnn_kernel<<<NCR, NTHR, RNN_SMEM>>>(inputs, emb, bi, bf, bo, bc);
    fin_kernel<<<SS + (2 * HH * BB) / NTHR, NTHR>>>(out, out_size);
}

// round 13
// speedup vs baseline: 1.0025x; 1.0025x over previous
#include <cuda_runtime.h>
#include <cuda_fp16.h>
#include <cstdint>

#define BB   64
#define SS   1024
#define EE   128
#define HH   512
#define GG   2048
#define NTHR 256
#define NCR  64        // rnn CTAs
#define HPC  8         // h columns per CTA
#define MRR  32        // D rows per CTA = 4 gates x 8 h

// ---- rnn dynamic smem layout (bytes) ----
#define A_BYTES  (MRR * HH * 2)          // 32768 fp16 Wh tile (1024B rows, swizzled)
#define B_BYTES  (BB * HH * 2)           // 65536 fp16 H tile (1024B rows, swizzled)
#define WX_OFF   (A_BYTES + B_BYTES)     // 98304: Wx tile [32 m][128 k] fp16, 256B rows
#define WX_BYTES (MRR * EE * 2)          // 8192
#define XS_OFF   (WX_OFF + WX_BYTES)     // 106496: X tile [64 b][128 k] fp16, 256B rows
#define XS_BYTES (BB * EE * 2)           // 16384
#define G_OFF    (XS_OFF + XS_BYTES)     // 122880: Gsm float[32][72]
#define G_BYTES  (MRR * 72 * 4)          // 9216
#define HN_OFF   (G_OFF + G_BYTES)       // 132096: HnSm half[8][66]
#define HN_BYTES (8 * 66 * 2)            // 1056
#define YS_OFF2  ((HN_OFF + HN_BYTES + 15) & ~15)
#define YS_BYTES (8 * 72 * 4)            // 2304
#define RNN_SMEM (YS_OFF2 + YS_BYTES)

// ---------------- module-scope scratch ----------------
__device__ __align__(128) __half        g_Hbuf[2][BB * HH];           // [b][h] fp16
__device__ __align__(128) float         g_Cbuf[HH * BB];              // [h][b]
__device__ __align__(128) float         g_Hfin[HH * BB];              // [h][b]
__device__ __align__(128) float         g_weff[HH];
__device__ __align__(128) float         g_beff[1];
__device__ __align__(128) float         g_party[(size_t)NCR * SS * BB];
__device__ __align__(128) unsigned      g_bar[SS];                    // step arrival counters
__device__ __align__(128) unsigned char g_Abuf[(size_t)NCR * A_BYTES];   // Wh images
__device__ __align__(128) unsigned char g_Wxbuf[(size_t)NCR * WX_BYTES]; // Wx images

__device__ __forceinline__ float sigf(float x)   { return 1.f / (1.f + __expf(-x)); }
__device__ __forceinline__ float tanhf_(float x) { return 2.f / (1.f + __expf(-2.f * x)) - 1.f; }

__device__ __forceinline__ uint32_t smem_u32(const void* p) {
    uint32_t a;
    asm("{ .reg .u64 t; cvta.to.shared.u64 t, %1; cvt.u32.u64 %0, t; }" : "=r"(a) : "l"(p));
    return a;
}
__device__ __forceinline__ void ldsm4(uint32_t* r, uint32_t addr) {
    asm volatile("ldmatrix.sync.aligned.m8n8.x4.shared.b16 {%0,%1,%2,%3}, [%4];"
                 : "=r"(r[0]), "=r"(r[1]), "=r"(r[2]), "=r"(r[3]) : "r"(addr));
}
__device__ __forceinline__ void mma16816(float* d, const uint32_t* a, const uint32_t* b) {
    asm volatile("mma.sync.aligned.m16n8k16.row.col.f32.f16.f16.f32 "
                 "{%0,%1,%2,%3}, {%4,%5,%6,%7}, {%8,%9}, {%0,%1,%2,%3};"
                 : "+f"(d[0]), "+f"(d[1]), "+f"(d[2]), "+f"(d[3])
                 : "r"(a[0]), "r"(a[1]), "r"(a[2]), "r"(a[3]), "r"(b[0]), "r"(b[1]));
}

// ---------------- init ----------------
__global__ void __launch_bounds__(NTHR) init_kernel(
    const float* __restrict__ H0, const float* __restrict__ C0,
    const float* __restrict__ Whq, const float* __restrict__ bq,
    const float* __restrict__ dw, const float* __restrict__ db)
{
    int t = blockIdx.x * blockDim.x + threadIdx.x;
    if (t < HH * BB) {
        int b = t >> 9, h = t & 511;
        g_Hbuf[0][t]       = __float2half_rn(H0[t]);   // [b][h]
        g_Cbuf[h * BB + b] = C0[t];
    }
    if (t < HH) {
        float a = 0.f;
        #pragma unroll 8
        for (int e = 0; e < EE; e++) a += Whq[t * EE + e] * dw[e];
        g_weff[t] = a;
    }
    if (t == 0) {
        float a = 0.f;
        for (int e = 0; e < EE; e++) a += bq[e] * dw[e];
        g_beff[0] = a + db[0];
    }
    if (t < SS) g_bar[t] = 0u;
}

// ---------------- prep: Wh images (1024B rows, swizzled fp16) ----------------
__global__ void __launch_bounds__(NTHR) prep_kernel(
    const float* __restrict__ Whi, const float* __restrict__ Whf,
    const float* __restrict__ Who, const float* __restrict__ Whc)
{
    int idx = blockIdx.x * blockDim.x + threadIdx.x;   // 64*32*512 = 1M
    int c = idx >> 14;
    int r = idx & 16383;
    int m = r >> 9;
    int k = r & 511;
    int g = m >> 3, u = m & 7;
    const float* W = (g == 0) ? Whi : (g == 1) ? Whf : (g == 2) ? Who : Whc;
    float v = W[(size_t)k * HH + c * HPC + u];
    uint32_t pos = (uint32_t)m * 1024 + (((uint32_t)k * 2) ^ (((uint32_t)m & 7) << 4));
    *(__half*)(g_Abuf + (size_t)c * A_BYTES + pos) = __float2half_rn(v);
}

// ---------------- prep_x: Wx images (256B rows, swizzled fp16) ---------------
__global__ void __launch_bounds__(NTHR) prep_x_kernel(
    const float* __restrict__ Wxi, const float* __restrict__ Wxf,
    const float* __restrict__ Wxo, const float* __restrict__ Wxc)
{
    int idx = blockIdx.x * blockDim.x + threadIdx.x;   // 64*32*128 = 262144
    int c = idx >> 12;
    int r = idx & 4095;
    int m = r >> 7;
    int k = r & 127;
    int g = m >> 3, u = m & 7;
    const float* W = (g == 0) ? Wxi : (g == 1) ? Wxf : (g == 2) ? Wxo : Wxc;
    float v = W[(size_t)k * HH + c * HPC + u];
    uint32_t pos = (uint32_t)m * 256 + (((uint32_t)k * 2) ^ (((uint32_t)m & 7) << 4));
    *(__half*)(g_Wxbuf + (size_t)c * WX_BYTES + pos) = __float2half_rn(v);
}

// ---------------- persistent recurrence, fused + pipelined X, 64 CTAs --------
__global__ void __launch_bounds__(NTHR, 1) rnn_kernel(
    const int* __restrict__ inputs, const float* __restrict__ emb,
    const float* __restrict__ bi,  const float* __restrict__ bf,
    const float* __restrict__ bo,  const float* __restrict__ bc)
{
    extern __shared__ __align__(16) unsigned char sm[];
    float*  Gsm  = (float*)(sm + G_OFF);
    __half* HnSm = (__half*)(sm + HN_OFF);
    float*  Ysm  = (float*)(sm + YS_OFF2);
    const uint32_t smb = smem_u32(sm);
    const uint32_t Ab  = smb;
    const uint32_t Bb  = smb + A_BYTES;
    const uint32_t WxB = smb + WX_OFF;
    const uint32_t XsB = smb + XS_OFF;

    const int t = threadIdx.x, lane = t & 31, wid = t >> 5;
    const int cta = blockIdx.x, hbase = cta * HPC;

    // load prebuilt Wh image (32 KB) + Wx image (8 KB)
    {
        const float4* asrc = (const float4*)(g_Abuf + (size_t)cta * A_BYTES);
        float4* adst = (float4*)sm;
        #pragma unroll
        for (int j = 0; j < 8; j++)
            adst[j * 256 + t] = __ldg(&asrc[j * 256 + t]);
        const float4* xsrc = (const float4*)(g_Wxbuf + (size_t)cta * WX_BYTES);
        float4* xdst = (float4*)(sm + WX_OFF);
        if (t < 128) {
            xdst[t]       = __ldg(&xsrc[t]);
            xdst[t + 128] = __ldg(&xsrc[t + 128]);
            xdst[t + 256] = __ldg(&xsrc[t + 256]);
            xdst[t + 384] = __ldg(&xsrc[t + 384]);
        }
    }

    // ldmatrix lane-address precompute (proven pattern)
    const int q = lane >> 3, r8 = lane & 7;
    const int mt = wid & 1;
    const int np = wid >> 1;
    const int arow = mt * 16 + r8 + ((q & 1) << 3);
    const uint32_t acol = (uint32_t)(q >> 1) * 16;
    const uint32_t aBase = Ab + (uint32_t)arow * 1024;
    const uint32_t axor  = ((uint32_t)arow & 7) << 4;
    const int brow = np * 16 + r8 + ((q >> 1) << 3);
    const uint32_t bcol = (uint32_t)(q & 1) * 16;
    const uint32_t bBase = Bb + (uint32_t)brow * 1024;
    const uint32_t bxor  = ((uint32_t)brow & 7) << 4;
    const uint32_t aBaseX = WxB + (uint32_t)arow * 256;
    const uint32_t bBaseX = XsB + (uint32_t)brow * 256;

    // epilogue role
    const int u = wid, eb = lane;
    float C0r = g_Cbuf[(hbase + u) * BB + eb];
    float C1r = g_Cbuf[(hbase + u) * BB + eb + 32];
    const float wef  = g_weff[hbase + u];
    const float bi_r = __ldg(&bi[hbase + u]);
    const float bf_r = __ldg(&bf[hbase + u]);
    const float bo_r = __ldg(&bo[hbase + u]);
    const float bc_r = __ldg(&bc[hbase + u]);
    __syncthreads();

    // X-gather role (constant across steps)
    const int bqi = t >> 2, part = t & 3;
    const int* tok_ptr = inputs + bqi * SS;

    // ---- X pipeline prologue: xpre holds emb rows for step 0; tok1 = token[1]
    float4 xpre[8];
    {
        int tok0 = __ldg(tok_ptr);
        const float4* src = (const float4*)(emb + (size_t)tok0 * EE) + part * 8;
        #pragma unroll
        for (int i = 0; i < 8; i++) xpre[i] = __ldg(&src[i]);
    }
    int tok1 = __ldg(tok_ptr + 1);

    for (int step = 0; step < SS; step++) {
        // (1) store prefetched X (fp32 regs -> fp16 swizzled smem) -- pure STS
        {
            #pragma unroll
            for (int i = 0; i < 4; i++) {
                float4 v0 = xpre[i * 2];
                float4 v1 = xpre[i * 2 + 1];
                __half2 h0 = __floats2half2_rn(v0.x, v0.y);
                __half2 h1 = __floats2half2_rn(v0.z, v0.w);
                __half2 h2 = __floats2half2_rn(v1.x, v1.y);
                __half2 h3 = __floats2half2_rn(v1.z, v1.w);
                uint4 uu = make_uint4(*(uint32_t*)&h0, *(uint32_t*)&h1,
                                      *(uint32_t*)&h2, *(uint32_t*)&h3);
                uint32_t col = (uint32_t)part * 64 + (uint32_t)i * 16;
                *(uint4*)(sm + XS_OFF + bqi * 256 + (col ^ (((uint32_t)bqi & 7) << 4))) = uu;
            }
        }
        // (2) issue X prefetch for step+1 (consumed next step; latency hidden)
        if (step + 1 < SS) {
            const float4* src = (const float4*)(emb + (size_t)tok1 * EE) + part * 8;
            #pragma unroll
            for (int i = 0; i < 8; i++) xpre[i] = __ldg(&src[i]);
            if (step + 2 < SS) tok1 = __ldg(tok_ptr + step + 2);
        }

        // (3) stage H [b][h] fp16 -> Bsm, per-row XOR swizzle (proven)
        {
            const float4* hs = (const float4*)g_Hbuf[step & 1];
            #pragma unroll
            for (int j = 0; j < 16; j++) {
                int i16 = j * 256 + t;
                float4 v = __ldcg(&hs[i16]);
                uint32_t b   = (uint32_t)i16 >> 6;
                uint32_t c16 = (uint32_t)i16 & 63;
                *(float4*)(sm + A_BYTES + b * 1024 + ((c16 * 16) ^ ((b & 7) << 4))) = v;
            }
        }
        __syncthreads();

        // (4) GEMM: 8 X k-slices + 32 H k-slices, shared accumulators
        float d0[4] = {0.f, 0.f, 0.f, 0.f};
        float d1[4] = {0.f, 0.f, 0.f, 0.f};
        #pragma unroll
        for (int ks = 0; ks < 8; ks++) {
            uint32_t a[4], b2[4];
            ldsm4(a,  aBaseX + (((uint32_t)ks * 32 + acol) ^ axor));
            ldsm4(b2, bBaseX + (((uint32_t)ks * 32 + bcol) ^ bxor));
            mma16816(d0, a, b2);
            mma16816(d1, a, b2 + 2);
        }
        #pragma unroll 8
        for (int ks = 0; ks < 32; ks++) {
            uint32_t a[4], b2[4];
            ldsm4(a,  aBase + (((uint32_t)ks * 32 + acol) ^ axor));
            ldsm4(b2, bBase + (((uint32_t)ks * 32 + bcol) ^ bxor));
            mma16816(d0, a, b2);
            mma16816(d1, a, b2 + 2);
        }
        {
            int g4 = lane >> 2, t4 = lane & 3;
            int mrow = mt * 16 + g4, nc = np * 16 + 2 * t4;
            *(float2*)&Gsm[mrow * 72 + nc]           = make_float2(d0[0], d0[1]);
            *(float2*)&Gsm[(mrow + 8) * 72 + nc]     = make_float2(d0[2], d0[3]);
            *(float2*)&Gsm[mrow * 72 + nc + 8]       = make_float2(d1[0], d1[1]);
            *(float2*)&Gsm[(mrow + 8) * 72 + nc + 8] = make_float2(d1[2], d1[3]);
        }
        __syncthreads();

        // (5) epilogue: 2 cells per thread (bias from registers)
        {
            float pi = bi_r + Gsm[( 0 + u) * 72 + eb];
            float pf = bf_r + Gsm[( 8 + u) * 72 + eb];
            float po = bo_r + Gsm[(16 + u) * 72 + eb];
            float pc = bc_r + Gsm[(24 + u) * 72 + eb];
            float I = sigf(pi), F = sigf(pf), O = sigf(po), Ct = tanhf_(pc);
            C0r = F * C0r + I * Ct;
            float Hn = O * tanhf_(C0r);
            HnSm[u * 66 + eb] = __float2half_rn(Hn);
            Ysm[u * 72 + eb]  = Hn * wef;
            if (step == SS - 1) { g_Hfin[(hbase + u) * BB + eb] = Hn; g_Cbuf[(hbase + u) * BB + eb] = C0r; }
        }
        {
            int bb = eb + 32;
            float pi = bi_r + Gsm[( 0 + u) * 72 + bb];
            float pf = bf_r + Gsm[( 8 + u) * 72 + bb];
            float po = bo_r + Gsm[(16 + u) * 72 + bb];
            float pc = bc_r + Gsm[(24 + u) * 72 + bb];
            float I = sigf(pi), F = sigf(pf), O = sigf(po), Ct = tanhf_(pc);
            C1r = F * C1r + I * Ct;
            float Hn = O * tanhf_(C1r);
            HnSm[u * 66 + bb] = __float2half_rn(Hn);
            Ysm[u * 72 + bb]  = Hn * wef;
            if (step == SS - 1) { g_Hfin[(hbase + u) * BB + bb] = Hn; g_Cbuf[(hbase + u) * BB + bb] = C1r; }
        }
        __syncthreads();

        // (6) pack new H (coalesced 16B per batch) + Y partial
        if (t < BB) {
            uint32_t p[4];
            #pragma unroll
            for (int uu = 0; uu < 4; uu++) {
                uint32_t lo = (uint32_t)__half_as_ushort(HnSm[(2 * uu)     * 66 + t]);
                uint32_t hi = (uint32_t)__half_as_ushort(HnSm[(2 * uu + 1) * 66 + t]);
                p[uu] = lo | (hi << 16);
            }
            *(uint4*)((unsigned char*)g_Hbuf[(step + 1) & 1] + (size_t)t * 1024 + (size_t)cta * 16)
                = make_uint4(p[0], p[1], p[2], p[3]);
        } else if (t < 2 * BB) {
            int bb = t - BB;
            float y = 0.f;
            #pragma unroll
            for (int uu = 0; uu < 8; uu++) y += Ysm[uu * 72 + bb];
            g_party[((size_t)cta * SS + step) * BB + bb] = y;
        }

        // (7) R5-proven 64-CTA barrier: atomic arrival + atomic poll
        __threadfence();
        __syncthreads();
        if (t == 0) {
            atomicAdd(&g_bar[step], 1u);
            while (atomicAdd(&g_bar[step], 0u) < (unsigned)NCR) { }
            __threadfence();
        }
        __syncthreads();
    }
}

// ---------------- finalize ----------------------------------------------------
__global__ void __launch_bounds__(NTHR) fin_kernel(float* __restrict__ out, int out_size)
{
    int blk = blockIdx.x, t = threadIdx.x;
    if (blk < SS) {
        if (t < BB) {
            float y = g_beff[0];
            #pragma unroll
            for (int c = 0; c < NCR; c++)
                y += g_party[((size_t)c * SS + blk) * BB + t];
            int o = blk * BB + t;
            if (o < out_size) out[o] = y;
        }
    } else {
        if (out_size < SS * BB + 2 * HH * BB) return;
        int i = (blk - SS) * NTHR + t;
        if (i < HH * BB) {
            int h = i >> 6, b = i & 63;
            out[SS * BB + b * HH + h] = g_Hfin[i];
        } else {
            int j = i - HH * BB;
            int h = j >> 6, b = j & 63;
            out[SS * BB + HH * BB + b * HH + h] = g_Cbuf[j];
        }
    }
}

// ---------------- launch ------------------------------------------------------
extern "C" void kernel_launch(void* const* d_in, const int* in_sizes, int n_in,
                              void* d_out, int out_size)
{
    const int*   inputs = (const int*)d_in[0];
    const float* H0  = (const float*)d_in[1];
    const float* C0  = (const float*)d_in[2];
    const float* emb = (const float*)d_in[3];
    const float* Wxi = (const float*)d_in[4];
    const float* Whi = (const float*)d_in[5];
    const float* bi  = (const float*)d_in[6];
    const float* Wxf = (const float*)d_in[7];
    const float* Whf = (const float*)d_in[8];
    const float* bf  = (const float*)d_in[9];
    const float* Wxo = (const float*)d_in[10];
    const float* Who = (const float*)d_in[11];
    const float* bo  = (const float*)d_in[12];
    const float* Wxc = (const float*)d_in[13];
    const float* Whc = (const float*)d_in[14];
    const float* bc  = (const float*)d_in[15];
    const float* Whq = (const float*)d_in[16];
    const float* bq  = (const float*)d_in[17];
    const float* dw  = (const float*)d_in[18];
    const float* db  = (const float*)d_in[19];
    float* out = (float*)d_out;

    cudaFuncSetAttribute(rnn_kernel, cudaFuncAttributeMaxDynamicSharedMemorySize, RNN_SMEM);

    init_kernel<<<128, NTHR>>>(H0, C0, Whq, bq, dw, db);
    prep_kernel<<<(NCR * MRR * HH) / NTHR, NTHR>>>(Whi, Whf, Who, Whc);
    prep_x_kernel<<<(NCR * MRR * EE) / NTHR, NTHR>>>(Wxi, Wxf, Wxo, Wxc);
    rnn_kernel<<<NCR, NTHR, RNN_SMEM>>>(inputs, emb, bi, bf, bo, bc);
    fin_kernel<<<SS + (2 * HH * BB) / NTHR, NTHR>>>(out, out_size);
}

// round 14
// speedup vs baseline: 1.3961x; 1.3927x over previous
#include <cuda_runtime.h>
#include <cuda_fp16.h>
#include <cstdint>

#define BB   64
#define SS   1024
#define EE   128
#define HH   512
#define NTHR 256
#define NGRP 2         // batch groups
#define NCG  64        // CTAs per group
#define NB   32        // batches per group
#define HPC  8         // h columns per CTA
#define MRR  32        // D rows per CTA = 4 gates x 8 h

// ---- rnn dynamic smem layout (bytes) ----
#define A_BYTES  (MRR * HH * 2)          // 32768 fp16 Wh tile (1024B rows, swizzled)
#define B_BYTES  (NB * HH * 2)           // 32768 fp16 H tile (1024B rows, swizzled)
#define WX_OFF   (A_BYTES + B_BYTES)     // Wx tile [32 m][128 k] fp16, 256B rows
#define WX_BYTES (MRR * EE * 2)          // 8192
#define XS_OFF   (WX_OFF + WX_BYTES)     // X tile [32 b][128 k] fp16, 256B rows
#define XS_BYTES (NB * EE * 2)           // 8192
#define G_OFF    (XS_OFF + XS_BYTES)     // Gsm float[32][36]
#define G_BYTES  (MRR * 36 * 4)          // 4608
#define HN_OFF   (G_OFF + G_BYTES)       // HnSm half[8][34]
#define HN_BYTES (8 * 34 * 2)            // 544
#define YS_OFF   ((HN_OFF + HN_BYTES + 15) & ~15)
#define YS_BYTES (8 * 36 * 4)            // 1152
#define RNN_SMEM (YS_OFF + YS_BYTES)     // ~88KB

// ---------------- module-scope scratch ----------------
__device__ __align__(128) __half        g_Hbuf[2][BB * HH];            // [b][h] fp16
__device__ __align__(128) float         g_Cbuf[HH * BB];               // [h][b]
__device__ __align__(128) float         g_Hfin[HH * BB];               // [h][b]
__device__ __align__(128) float         g_weff[HH];
__device__ __align__(128) float         g_beff[1];
__device__ __align__(128) float         g_party[(size_t)NGRP * NCG * SS * NB];
__device__ __align__(128) unsigned      g_bar[NGRP * SS];              // per-group arrival counters
__device__ __align__(128) unsigned char g_Abuf[(size_t)NCG * A_BYTES];    // Wh images (per cidx)
__device__ __align__(128) unsigned char g_Wxbuf[(size_t)NCG * WX_BYTES];  // Wx images (per cidx)

__device__ __forceinline__ float sigf(float x)   { return 1.f / (1.f + __expf(-x)); }
__device__ __forceinline__ float tanhf_(float x) { return 2.f / (1.f + __expf(-2.f * x)) - 1.f; }

__device__ __forceinline__ uint32_t smem_u32(const void* p) {
    uint32_t a;
    asm("{ .reg .u64 t; cvta.to.shared.u64 t, %1; cvt.u32.u64 %0, t; }" : "=r"(a) : "l"(p));
    return a;
}
__device__ __forceinline__ void ldsm4(uint32_t* r, uint32_t addr) {
    asm volatile("ldmatrix.sync.aligned.m8n8.x4.shared.b16 {%0,%1,%2,%3}, [%4];"
                 : "=r"(r[0]), "=r"(r[1]), "=r"(r[2]), "=r"(r[3]) : "r"(addr));
}
__device__ __forceinline__ void ldsm2(uint32_t* r, uint32_t addr) {
    asm volatile("ldmatrix.sync.aligned.m8n8.x2.shared.b16 {%0,%1}, [%2];"
                 : "=r"(r[0]), "=r"(r[1]) : "r"(addr));
}
__device__ __forceinline__ void mma16816(float* d, const uint32_t* a, const uint32_t* b) {
    asm volatile("mma.sync.aligned.m16n8k16.row.col.f32.f16.f16.f32 "
                 "{%0,%1,%2,%3}, {%4,%5,%6,%7}, {%8,%9}, {%0,%1,%2,%3};"
                 : "+f"(d[0]), "+f"(d[1]), "+f"(d[2]), "+f"(d[3])
                 : "r"(a[0]), "r"(a[1]), "r"(a[2]), "r"(a[3]), "r"(b[0]), "r"(b[1]));
}

// ---------------- init ----------------
__global__ void __launch_bounds__(NTHR) init_kernel(
    const float* __restrict__ H0, const float* __restrict__ C0,
    const float* __restrict__ Whq, const float* __restrict__ bq,
    const float* __restrict__ dw, const float* __restrict__ db)
{
    int t = blockIdx.x * blockDim.x + threadIdx.x;
    if (t < HH * BB) {
        int b = t >> 9, h = t & 511;
        g_Hbuf[0][t]       = __float2half_rn(H0[t]);   // [b][h]
        g_Cbuf[h * BB + b] = C0[t];
    }
    if (t < HH) {
        float a = 0.f;
        #pragma unroll 8
        for (int e = 0; e < EE; e++) a += Whq[t * EE + e] * dw[e];
        g_weff[t] = a;
    }
    if (t == 0) {
        float a = 0.f;
        for (int e = 0; e < EE; e++) a += bq[e] * dw[e];
        g_beff[0] = a + db[0];
    }
    if (t < NGRP * SS) g_bar[t] = 0u;
}

// ---------------- prep: Wh images (1024B rows, swizzled fp16) ----------------
__global__ void __launch_bounds__(NTHR) prep_kernel(
    const float* __restrict__ Whi, const float* __restrict__ Whf,
    const float* __restrict__ Who, const float* __restrict__ Whc)
{
    int idx = blockIdx.x * blockDim.x + threadIdx.x;   // 64*32*512 = 1M
    int c = idx >> 14;
    int r = idx & 16383;
    int m = r >> 9;
    int k = r & 511;
    int g = m >> 3, u = m & 7;
    const float* W = (g == 0) ? Whi : (g == 1) ? Whf : (g == 2) ? Who : Whc;
    float v = W[(size_t)k * HH + c * HPC + u];
    uint32_t pos = (uint32_t)m * 1024 + (((uint32_t)k * 2) ^ (((uint32_t)m & 7) << 4));
    *(__half*)(g_Abuf + (size_t)c * A_BYTES + pos) = __float2half_rn(v);
}

// ---------------- prep_x: Wx images (256B rows, swizzled fp16) ---------------
__global__ void __launch_bounds__(NTHR) prep_x_kernel(
    const float* __restrict__ Wxi, const float* __restrict__ Wxf,
    const float* __restrict__ Wxo, const float* __restrict__ Wxc)
{
    int idx = blockIdx.x * blockDim.x + threadIdx.x;   // 64*32*128 = 262144
    int c = idx >> 12;
    int r = idx & 4095;
    int m = r >> 7;
    int k = r & 127;
    int g = m >> 3, u = m & 7;
    const float* W = (g == 0) ? Wxi : (g == 1) ? Wxf : (g == 2) ? Wxo : Wxc;
    float v = W[(size_t)k * HH + c * HPC + u];
    uint32_t pos = (uint32_t)m * 256 + (((uint32_t)k * 2) ^ (((uint32_t)m & 7) << 4));
    *(__half*)(g_Wxbuf + (size_t)c * WX_BYTES + pos) = __float2half_rn(v);
}

// ---------------- persistent recurrence: 2 batch groups x 64 CTAs ------------
__global__ void __launch_bounds__(NTHR, 1) rnn_kernel(
    const int* __restrict__ inputs, const float* __restrict__ emb,
    const float* __restrict__ bi,  const float* __restrict__ bf,
    const float* __restrict__ bo,  const float* __restrict__ bc)
{
    extern __shared__ __align__(16) unsigned char sm[];
    float*  Gsm  = (float*)(sm + G_OFF);
    __half* HnSm = (__half*)(sm + HN_OFF);
    float*  Ysm  = (float*)(sm + YS_OFF);
    const uint32_t smb = smem_u32(sm);
    const uint32_t Ab  = smb;
    const uint32_t Bb  = smb + A_BYTES;
    const uint32_t WxB = smb + WX_OFF;
    const uint32_t XsB = smb + XS_OFF;

    const int t = threadIdx.x, lane = t & 31, wid = t >> 5;
    const int cta  = blockIdx.x;
    const int grp  = cta >> 6;            // batch group 0/1
    const int cidx = cta & 63;            // h-slice index within group
    const int hbase = cidx * HPC;
    const int bbase = grp * NB;

    // load prebuilt Wh image (32 KB) + Wx image (8 KB)
    {
        const float4* asrc = (const float4*)(g_Abuf + (size_t)cidx * A_BYTES);
        float4* adst = (float4*)sm;
        #pragma unroll
        for (int j = 0; j < 8; j++)
            adst[j * 256 + t] = __ldg(&asrc[j * 256 + t]);
        const float4* xsrc = (const float4*)(g_Wxbuf + (size_t)cidx * WX_BYTES);
        float4* xdst = (float4*)(sm + WX_OFF);
        if (t < 128) {
            xdst[t]       = __ldg(&xsrc[t]);
            xdst[t + 128] = __ldg(&xsrc[t + 128]);
            xdst[t + 256] = __ldg(&xsrc[t + 256]);
            xdst[t + 384] = __ldg(&xsrc[t + 384]);
        }
    }

    // GEMM lane mapping: warp slot (mt 0..1, nt 0..3): M 16-rows x N 8-cols
    const int q = lane >> 3, r8 = lane & 7;
    const int mt = wid >> 2;
    const int nt = wid & 3;
    const int arow = mt * 16 + r8 + ((q & 1) << 3);
    const uint32_t acol   = (uint32_t)(q >> 1) * 16;
    const uint32_t aBase  = Ab  + (uint32_t)arow * 1024;
    const uint32_t aBaseX = WxB + (uint32_t)arow * 256;
    const uint32_t axor   = ((uint32_t)arow & 7) << 4;
    const int l16 = lane & 15;
    const int brow = nt * 8 + (l16 & 7);
    const uint32_t bcol   = (uint32_t)(l16 >> 3) * 16;
    const uint32_t bBase  = Bb  + (uint32_t)brow * 1024;
    const uint32_t bBaseX = XsB + (uint32_t)brow * 256;
    const uint32_t bxor   = ((uint32_t)brow & 7) << 4;

    // epilogue role: 1 cell per thread: h = hbase+u, b = bbase+eb
    const int u = wid, eb = lane;
    float Cr = g_Cbuf[(hbase + u) * BB + bbase + eb];
    const float wef  = g_weff[hbase + u];
    const float bi_r = __ldg(&bi[hbase + u]);
    const float bf_r = __ldg(&bf[hbase + u]);
    const float bo_r = __ldg(&bo[hbase + u]);
    const float bc_r = __ldg(&bc[hbase + u]);
    __syncthreads();

    // X-gather role: 32 rows x 8 parts (16 floats each)
    const int bqi = t >> 3, part = t & 7;
    const int* tok_ptr = inputs + (bbase + bqi) * SS;

    // X pipeline prologue
    float4 xpre[4];
    {
        int tok0 = __ldg(tok_ptr);
        const float4* src = (const float4*)(emb + (size_t)tok0 * EE) + part * 4;
        #pragma unroll
        for (int i = 0; i < 4; i++) xpre[i] = __ldg(&src[i]);
    }
    int tok1 = __ldg(tok_ptr + 1);

    unsigned* barp = g_bar + grp * SS;

    for (int step = 0; step < SS; step++) {
        // (1) store prefetched X (fp32 regs -> fp16 swizzled smem)
        {
            __half2 h0 = __floats2half2_rn(xpre[0].x, xpre[0].y);
            __half2 h1 = __floats2half2_rn(xpre[0].z, xpre[0].w);
            __half2 h2 = __floats2half2_rn(xpre[1].x, xpre[1].y);
            __half2 h3 = __floats2half2_rn(xpre[1].z, xpre[1].w);
            __half2 h4 = __floats2half2_rn(xpre[2].x, xpre[2].y);
            __half2 h5 = __floats2half2_rn(xpre[2].z, xpre[2].w);
            __half2 h6 = __floats2half2_rn(xpre[3].x, xpre[3].y);
            __half2 h7 = __floats2half2_rn(xpre[3].z, xpre[3].w);
            uint4 u0 = make_uint4(*(uint32_t*)&h0, *(uint32_t*)&h1,
                                  *(uint32_t*)&h2, *(uint32_t*)&h3);
            uint4 u1 = make_uint4(*(uint32_t*)&h4, *(uint32_t*)&h5,
                                  *(uint32_t*)&h6, *(uint32_t*)&h7);
            uint32_t xo = ((uint32_t)bqi & 7) << 4;
            uint32_t c0 = (uint32_t)part * 32;
            *(uint4*)(sm + XS_OFF + bqi * 256 + (c0 ^ xo))        = u0;
            *(uint4*)(sm + XS_OFF + bqi * 256 + ((c0 + 16) ^ xo)) = u1;
        }
        // (2) issue X prefetch for step+1
        if (step + 1 < SS) {
            const float4* src = (const float4*)(emb + (size_t)tok1 * EE) + part * 4;
            #pragma unroll
            for (int i = 0; i < 4; i++) xpre[i] = __ldg(&src[i]);
            if (step + 2 < SS) tok1 = __ldg(tok_ptr + step + 2);
        }

        // (3) stage this group's H slice [32 b][512 h] fp16 -> Bsm
        {
            const float4* hs = (const float4*)g_Hbuf[step & 1] + bbase * 64;
            #pragma unroll
            for (int j = 0; j < 8; j++) {
                int i16 = j * 256 + t;
                float4 v = __ldcg(&hs[i16]);
                uint32_t b   = (uint32_t)i16 >> 6;
                uint32_t c16 = (uint32_t)i16 & 63;
                *(float4*)(sm + A_BYTES + b * 1024 + ((c16 * 16) ^ ((b & 7) << 4))) = v;
            }
        }
        __syncthreads();

        // (4) GEMM: 8 X k-slices + 32 H k-slices, one accumulator
        float d0[4] = {0.f, 0.f, 0.f, 0.f};
        #pragma unroll
        for (int ks = 0; ks < 8; ks++) {
            uint32_t a[4], b2[2];
            ldsm4(a,  aBaseX + (((uint32_t)ks * 32 + acol) ^ axor));
            ldsm2(b2, bBaseX + (((uint32_t)ks * 32 + bcol) ^ bxor));
            mma16816(d0, a, b2);
        }
        #pragma unroll 8
        for (int ks = 0; ks < 32; ks++) {
            uint32_t a[4], b2[2];
            ldsm4(a,  aBase + (((uint32_t)ks * 32 + acol) ^ axor));
            ldsm2(b2, bBase + (((uint32_t)ks * 32 + bcol) ^ bxor));
            mma16816(d0, a, b2);
        }
        {
            int g4 = lane >> 2, t4 = lane & 3;
            int mrow = mt * 16 + g4, nc = nt * 8 + 2 * t4;
            *(float2*)&Gsm[mrow * 36 + nc]       = make_float2(d0[0], d0[1]);
            *(float2*)&Gsm[(mrow + 8) * 36 + nc] = make_float2(d0[2], d0[3]);
        }
        __syncthreads();

        // (5) epilogue: exactly 1 cell per thread
        {
            float pi = bi_r + Gsm[( 0 + u) * 36 + eb];
            float pf = bf_r + Gsm[( 8 + u) * 36 + eb];
            float po = bo_r + Gsm[(16 + u) * 36 + eb];
            float pc = bc_r + Gsm[(24 + u) * 36 + eb];
            float I = sigf(pi), F = sigf(pf), O = sigf(po), Ct = tanhf_(pc);
            Cr = F * Cr + I * Ct;
            float Hn = O * tanhf_(Cr);
            HnSm[u * 34 + eb] = __float2half_rn(Hn);
            Ysm[u * 36 + eb]  = Hn * wef;
            if (step == SS - 1) {
                g_Hfin[(hbase + u) * BB + bbase + eb] = Hn;
                g_Cbuf[(hbase + u) * BB + bbase + eb] = Cr;
            }
        }
        __syncthreads();

        // (6) pack new H (16B per batch) + Y partial
        if (t < NB) {
            uint32_t p[4];
            #pragma unroll
            for (int uu = 0; uu < 4; uu++) {
                uint32_t lo = (uint32_t)__half_as_ushort(HnSm[(2 * uu)     * 34 + t]);
                uint32_t hi = (uint32_t)__half_as_ushort(HnSm[(2 * uu + 1) * 34 + t]);
                p[uu] = lo | (hi << 16);
            }
            *(uint4*)((unsigned char*)g_Hbuf[(step + 1) & 1]
                      + (size_t)(bbase + t) * 1024 + (size_t)cidx * 16)
                = make_uint4(p[0], p[1], p[2], p[3]);
        } else if (t < 2 * NB) {
            int bb = t - NB;
            float y = 0.f;
            #pragma unroll
            for (int uu = 0; uu < 8; uu++) y += Ysm[uu * 36 + bb];
            g_party[(size_t)cta * (SS * NB) + (size_t)step * NB + bb] = y;
        }

        // (7) group-local 64-CTA barrier (proven pattern)
        __threadfence();
        __syncthreads();
        if (t == 0) {
            atomicAdd(&barp[step], 1u);
            while (atomicAdd(&barp[step], 0u) < (unsigned)NCG) { }
            __threadfence();
        }
        __syncthreads();
    }
}

// ---------------- finalize ----------------------------------------------------
__global__ void __launch_bounds__(NTHR) fin_kernel(float* __restrict__ out, int out_size)
{
    int blk = blockIdx.x, t = threadIdx.x;
    if (blk < SS) {
        if (t < BB) {
            int g = t >> 5, bw = t & 31;
            float y = g_beff[0];
            #pragma unroll
            for (int c = 0; c < NCG; c++)
                y += g_party[(size_t)(g * NCG + c) * (SS * NB) + (size_t)blk * NB + bw];
            int o = blk * BB + t;
            if (o < out_size) out[o] = y;
        }
    } else {
        if (out_size < SS * BB + 2 * HH * BB) return;
        int i = (blk - SS) * NTHR + t;
        if (i < HH * BB) {
            int h = i >> 6, b = i & 63;
            out[SS * BB + b * HH + h] = g_Hfin[i];
        } else {
            int j = i - HH * BB;
            int h = j >> 6, b = j & 63;
            out[SS * BB + HH * BB + b * HH + h] = g_Cbuf[j];
        }
    }
}

// ---------------- launch ------------------------------------------------------
extern "C" void kernel_launch(void* const* d_in, const int* in_sizes, int n_in,
                              void* d_out, int out_size)
{
    const int*   inputs = (const int*)d_in[0];
    const float* H0  = (const float*)d_in[1];
    const float* C0  = (const float*)d_in[2];
    const float* emb = (const float*)d_in[3];
    const float* Wxi = (const float*)d_in[4];
    const float* Whi = (const float*)d_in[5];
    const float* bi  = (const float*)d_in[6];
    const float* Wxf = (const float*)d_in[7];
    const float* Whf = (const float*)d_in[8];
    const float* bf  = (const float*)d_in[9];
    const float* Wxo = (const float*)d_in[10];
    const float* Who = (const float*)d_in[11];
    const float* bo  = (const float*)d_in[12];
    const float* Wxc = (const float*)d_in[13];
    const float* Whc = (const float*)d_in[14];
    const float* bc  = (const float*)d_in[15];
    const float* Whq = (const float*)d_in[16];
    const float* bq  = (const float*)d_in[17];
    const float* dw  = (const float*)d_in[18];
    const float* db  = (const float*)d_in[19];
    float* out = (float*)d_out;

    cudaFuncSetAttribute(rnn_kernel, cudaFuncAttributeMaxDynamicSharedMemorySize, RNN_SMEM);

    init_kernel<<<128, NTHR>>>(H0, C0, Whq, bq, dw, db);
    prep_kernel<<<(NCG * MRR * HH) / NTHR, NTHR>>>(Whi, Whf, Who, Whc);
    prep_x_kernel<<<(NCG * MRR * EE) / NTHR, NTHR>>>(Wxi, Wxf, Wxo, Wxc);
    rnn_kernel<<<NGRP * NCG, NTHR, RNN_SMEM>>>(inputs, emb, bi, bf, bo, bc);
    fin_kernel<<<SS + (2 * HH * BB) / NTHR, NTHR>>>(out, out_size);
}

// round 15
// speedup vs baseline: 1.5660x; 1.1217x over previous
#include <cuda_runtime.h>
#include <cuda_fp16.h>
#include <cstdint>

#define BB   64
#define SS   1024
#define EE   128
#define HH   512
#define NTHR 256
#define NGRP 2         // batch groups
#define NCG  64        // CTAs per group
#define NB   32        // batches per group
#define HPC  8         // h columns per CTA
#define MRR  32        // D rows per CTA = 4 gates x 8 h

// ---- rnn dynamic smem layout (bytes) ----
#define A_BYTES  (MRR * HH * 2)          // 32768 fp16 Wh tile (1024B rows, swizzled)
#define B_BYTES  (NB * HH * 2)           // 32768 fp16 H tile (1024B rows, swizzled)
#define WX_OFF   (A_BYTES + B_BYTES)     // Wx tile [32 m][128 k] fp16, 256B rows
#define WX_BYTES (MRR * EE * 2)          // 8192
#define XS_OFF   (WX_OFF + WX_BYTES)     // X tile [32 b][128 k] fp16, 256B rows
#define XS_BYTES (NB * EE * 2)           // 8192
#define G_OFF    (XS_OFF + XS_BYTES)     // Gsm float[32][36]
#define G_BYTES  (MRR * 36 * 4)          // 4608
#define HN_OFF   (G_OFF + G_BYTES)       // HnSm half[8][34]
#define HN_BYTES (8 * 34 * 2)            // 544
#define YS_OFF   ((HN_OFF + HN_BYTES + 15) & ~15)
#define YS_BYTES (8 * 36 * 4)            // 1152
#define RNN_SMEM (YS_OFF + YS_BYTES)     // ~88KB

// ---------------- module-scope scratch ----------------
__device__ __align__(128) __half        g_Hbuf[2][BB * HH];            // [b][h] fp16
__device__ __align__(128) float         g_Cbuf[HH * BB];               // [h][b]
__device__ __align__(128) float         g_Hfin[HH * BB];               // [h][b]
__device__ __align__(128) float         g_weff[HH];
__device__ __align__(128) float         g_beff[1];
__device__ __align__(128) float         g_party[(size_t)NGRP * NCG * SS * NB];
__device__ __align__(128) unsigned      g_bar[NGRP * SS];              // per-group arrival counters
__device__ __align__(128) unsigned char g_Abuf[(size_t)NCG * A_BYTES];    // Wh images (per cidx)
__device__ __align__(128) unsigned char g_Wxbuf[(size_t)NCG * WX_BYTES];  // Wx images (per cidx)

// fast activations: tanh.approx (1 MUFU) instead of ex2+rcp (2 MUFU)
__device__ __forceinline__ float tanh_fast(float x) {
    float y;
    asm("tanh.approx.f32 %0, %1;" : "=f"(y) : "f"(x));
    return y;
}
__device__ __forceinline__ float sigf(float x)   { return fmaf(0.5f, tanh_fast(0.5f * x), 0.5f); }
__device__ __forceinline__ float tanhf_(float x) { return tanh_fast(x); }

__device__ __forceinline__ uint32_t smem_u32(const void* p) {
    uint32_t a;
    asm("{ .reg .u64 t; cvta.to.shared.u64 t, %1; cvt.u32.u64 %0, t; }" : "=r"(a) : "l"(p));
    return a;
}
__device__ __forceinline__ void ldsm4(uint32_t* r, uint32_t addr) {
    asm volatile("ldmatrix.sync.aligned.m8n8.x4.shared.b16 {%0,%1,%2,%3}, [%4];"
                 : "=r"(r[0]), "=r"(r[1]), "=r"(r[2]), "=r"(r[3]) : "r"(addr));
}
__device__ __forceinline__ void ldsm2(uint32_t* r, uint32_t addr) {
    asm volatile("ldmatrix.sync.aligned.m8n8.x2.shared.b16 {%0,%1}, [%2];"
                 : "=r"(r[0]), "=r"(r[1]) : "r"(addr));
}
__device__ __forceinline__ void mma16816(float* d, const uint32_t* a, const uint32_t* b) {
    asm volatile("mma.sync.aligned.m16n8k16.row.col.f32.f16.f16.f32 "
                 "{%0,%1,%2,%3}, {%4,%5,%6,%7}, {%8,%9}, {%0,%1,%2,%3};"
                 : "+f"(d[0]), "+f"(d[1]), "+f"(d[2]), "+f"(d[3])
                 : "r"(a[0]), "r"(a[1]), "r"(a[2]), "r"(a[3]), "r"(b[0]), "r"(b[1]));
}

// ---------------- init ----------------
__global__ void __launch_bounds__(NTHR) init_kernel(
    const float* __restrict__ H0, const float* __restrict__ C0,
    const float* __restrict__ Whq, const float* __restrict__ bq,
    const float* __restrict__ dw, const float* __restrict__ db)
{
    int t = blockIdx.x * blockDim.x + threadIdx.x;
    if (t < HH * BB) {
        int b = t >> 9, h = t & 511;
        g_Hbuf[0][t]       = __float2half_rn(H0[t]);   // [b][h]
        g_Cbuf[h * BB + b] = C0[t];
    }
    if (t < HH) {
        float a = 0.f;
        #pragma unroll 8
        for (int e = 0; e < EE; e++) a += Whq[t * EE + e] * dw[e];
        g_weff[t] = a;
    }
    if (t == 0) {
        float a = 0.f;
        for (int e = 0; e < EE; e++) a += bq[e] * dw[e];
        g_beff[0] = a + db[0];
    }
    if (t < NGRP * SS) g_bar[t] = 0u;
}

// ---------------- prep: Wh images (1024B rows, swizzled fp16) ----------------
__global__ void __launch_bounds__(NTHR) prep_kernel(
    const float* __restrict__ Whi, const float* __restrict__ Whf,
    const float* __restrict__ Who, const float* __restrict__ Whc)
{
    int idx = blockIdx.x * blockDim.x + threadIdx.x;   // 64*32*512 = 1M
    int c = idx >> 14;
    int r = idx & 16383;
    int m = r >> 9;
    int k = r & 511;
    int g = m >> 3, u = m & 7;
    const float* W = (g == 0) ? Whi : (g == 1) ? Whf : (g == 2) ? Who : Whc;
    float v = W[(size_t)k * HH + c * HPC + u];
    uint32_t pos = (uint32_t)m * 1024 + (((uint32_t)k * 2) ^ (((uint32_t)m & 7) << 4));
    *(__half*)(g_Abuf + (size_t)c * A_BYTES + pos) = __float2half_rn(v);
}

// ---------------- prep_x: Wx images (256B rows, swizzled fp16) ---------------
__global__ void __launch_bounds__(NTHR) prep_x_kernel(
    const float* __restrict__ Wxi, const float* __restrict__ Wxf,
    const float* __restrict__ Wxo, const float* __restrict__ Wxc)
{
    int idx = blockIdx.x * blockDim.x + threadIdx.x;   // 64*32*128 = 262144
    int c = idx >> 12;
    int r = idx & 4095;
    int m = r >> 7;
    int k = r & 127;
    int g = m >> 3, u = m & 7;
    const float* W = (g == 0) ? Wxi : (g == 1) ? Wxf : (g == 2) ? Wxo : Wxc;
    float v = W[(size_t)k * HH + c * HPC + u];
    uint32_t pos = (uint32_t)m * 256 + (((uint32_t)k * 2) ^ (((uint32_t)m & 7) << 4));
    *(__half*)(g_Wxbuf + (size_t)c * WX_BYTES + pos) = __float2half_rn(v);
}

// ---------------- persistent recurrence: 2 batch groups x 64 CTAs ------------
__global__ void __launch_bounds__(NTHR, 1) rnn_kernel(
    const int* __restrict__ inputs, const float* __restrict__ emb,
    const float* __restrict__ bi,  const float* __restrict__ bf,
    const float* __restrict__ bo,  const float* __restrict__ bc)
{
    extern __shared__ __align__(16) unsigned char sm[];
    float*  Gsm  = (float*)(sm + G_OFF);
    __half* HnSm = (__half*)(sm + HN_OFF);
    float*  Ysm  = (float*)(sm + YS_OFF);
    const uint32_t smb = smem_u32(sm);
    const uint32_t Ab  = smb;
    const uint32_t Bb  = smb + A_BYTES;
    const uint32_t WxB = smb + WX_OFF;
    const uint32_t XsB = smb + XS_OFF;

    const int t = threadIdx.x, lane = t & 31, wid = t >> 5;
    const int cta  = blockIdx.x;
    const int grp  = cta >> 6;            // batch group 0/1
    const int cidx = cta & 63;            // h-slice index within group
    const int hbase = cidx * HPC;
    const int bbase = grp * NB;

    // load prebuilt Wh image (32 KB) + Wx image (8 KB)
    {
        const float4* asrc = (const float4*)(g_Abuf + (size_t)cidx * A_BYTES);
        float4* adst = (float4*)sm;
        #pragma unroll
        for (int j = 0; j < 8; j++)
            adst[j * 256 + t] = __ldg(&asrc[j * 256 + t]);
        const float4* xsrc = (const float4*)(g_Wxbuf + (size_t)cidx * WX_BYTES);
        float4* xdst = (float4*)(sm + WX_OFF);
        if (t < 128) {
            xdst[t]       = __ldg(&xsrc[t]);
            xdst[t + 128] = __ldg(&xsrc[t + 128]);
            xdst[t + 256] = __ldg(&xsrc[t + 256]);
            xdst[t + 384] = __ldg(&xsrc[t + 384]);
        }
    }

    // GEMM lane mapping: warp slot (mt 0..1, nt 0..3): M 16-rows x N 8-cols
    const int q = lane >> 3, r8 = lane & 7;
    const int mt = wid >> 2;
    const int nt = wid & 3;
    const int arow = mt * 16 + r8 + ((q & 1) << 3);
    const uint32_t acol   = (uint32_t)(q >> 1) * 16;
    const uint32_t aBase  = Ab  + (uint32_t)arow * 1024;
    const uint32_t aBaseX = WxB + (uint32_t)arow * 256;
    const uint32_t axor   = ((uint32_t)arow & 7) << 4;
    const int l16 = lane & 15;
    const int brow = nt * 8 + (l16 & 7);
    const uint32_t bcol   = (uint32_t)(l16 >> 3) * 16;
    const uint32_t bBase  = Bb  + (uint32_t)brow * 1024;
    const uint32_t bBaseX = XsB + (uint32_t)brow * 256;
    const uint32_t bxor   = ((uint32_t)brow & 7) << 4;

    // epilogue role: 1 cell per thread: h = hbase+u, b = bbase+eb
    const int u = wid, eb = lane;
    float Cr = g_Cbuf[(hbase + u) * BB + bbase + eb];
    const float wef  = g_weff[hbase + u];
    const float bi_r = __ldg(&bi[hbase + u]);
    const float bf_r = __ldg(&bf[hbase + u]);
    const float bo_r = __ldg(&bo[hbase + u]);
    const float bc_r = __ldg(&bc[hbase + u]);
    __syncthreads();

    // X-gather role: 32 rows x 8 parts (16 floats each)
    const int bqi = t >> 3, part = t & 7;
    const int* tok_ptr = inputs + (bbase + bqi) * SS;

    // X pipeline prologue
    float4 xpre[4];
    {
        int tok0 = __ldg(tok_ptr);
        const float4* src = (const float4*)(emb + (size_t)tok0 * EE) + part * 4;
        #pragma unroll
        for (int i = 0; i < 4; i++) xpre[i] = __ldg(&src[i]);
    }
    int tok1 = __ldg(tok_ptr + 1);

    unsigned* barp = g_bar + grp * SS;

    for (int step = 0; step < SS; step++) {
        // (1) store prefetched X (fp32 regs -> fp16 swizzled smem)
        {
            __half2 h0 = __floats2half2_rn(xpre[0].x, xpre[0].y);
            __half2 h1 = __floats2half2_rn(xpre[0].z, xpre[0].w);
            __half2 h2 = __floats2half2_rn(xpre[1].x, xpre[1].y);
            __half2 h3 = __floats2half2_rn(xpre[1].z, xpre[1].w);
            __half2 h4 = __floats2half2_rn(xpre[2].x, xpre[2].y);
            __half2 h5 = __floats2half2_rn(xpre[2].z, xpre[2].w);
            __half2 h6 = __floats2half2_rn(xpre[3].x, xpre[3].y);
            __half2 h7 = __floats2half2_rn(xpre[3].z, xpre[3].w);
            uint4 u0 = make_uint4(*(uint32_t*)&h0, *(uint32_t*)&h1,
                                  *(uint32_t*)&h2, *(uint32_t*)&h3);
            uint4 u1 = make_uint4(*(uint32_t*)&h4, *(uint32_t*)&h5,
                                  *(uint32_t*)&h6, *(uint32_t*)&h7);
            uint32_t xo = ((uint32_t)bqi & 7) << 4;
            uint32_t c0 = (uint32_t)part * 32;
            *(uint4*)(sm + XS_OFF + bqi * 256 + (c0 ^ xo))        = u0;
            *(uint4*)(sm + XS_OFF + bqi * 256 + ((c0 + 16) ^ xo)) = u1;
        }
        // (2) issue X prefetch for step+1
        if (step + 1 < SS) {
            const float4* src = (const float4*)(emb + (size_t)tok1 * EE) + part * 4;
            #pragma unroll
            for (int i = 0; i < 4; i++) xpre[i] = __ldg(&src[i]);
            if (step + 2 < SS) tok1 = __ldg(tok_ptr + step + 2);
        }

        // (3) stage this group's H slice [32 b][512 h] fp16 -> Bsm
        {
            const float4* hs = (const float4*)g_Hbuf[step & 1] + bbase * 64;
            #pragma unroll
            for (int j = 0; j < 8; j++) {
                int i16 = j * 256 + t;
                float4 v = __ldcg(&hs[i16]);
                uint32_t b   = (uint32_t)i16 >> 6;
                uint32_t c16 = (uint32_t)i16 & 63;
                *(float4*)(sm + A_BYTES + b * 1024 + ((c16 * 16) ^ ((b & 7) << 4))) = v;
            }
        }
        __syncthreads();

        // (4) GEMM: 8 X k-slices + 32 H k-slices, DUAL accumulators (even/odd)
        float dA[4] = {0.f, 0.f, 0.f, 0.f};
        float dB[4] = {0.f, 0.f, 0.f, 0.f};
        #pragma unroll
        for (int ks = 0; ks < 8; ks += 2) {
            uint32_t a0[4], b0[2], a1[4], b1[2];
            ldsm4(a0, aBaseX + (((uint32_t)ks * 32 + acol) ^ axor));
            ldsm2(b0, bBaseX + (((uint32_t)ks * 32 + bcol) ^ bxor));
            ldsm4(a1, aBaseX + (((uint32_t)(ks + 1) * 32 + acol) ^ axor));
            ldsm2(b1, bBaseX + (((uint32_t)(ks + 1) * 32 + bcol) ^ bxor));
            mma16816(dA, a0, b0);
            mma16816(dB, a1, b1);
        }
        #pragma unroll 8
        for (int ks = 0; ks < 32; ks += 2) {
            uint32_t a0[4], b0[2], a1[4], b1[2];
            ldsm4(a0, aBase + (((uint32_t)ks * 32 + acol) ^ axor));
            ldsm2(b0, bBase + (((uint32_t)ks * 32 + bcol) ^ bxor));
            ldsm4(a1, aBase + (((uint32_t)(ks + 1) * 32 + acol) ^ axor));
            ldsm2(b1, bBase + (((uint32_t)(ks + 1) * 32 + bcol) ^ bxor));
            mma16816(dA, a0, b0);
            mma16816(dB, a1, b1);
        }
        {
            int g4 = lane >> 2, t4 = lane & 3;
            int mrow = mt * 16 + g4, nc = nt * 8 + 2 * t4;
            *(float2*)&Gsm[mrow * 36 + nc]       = make_float2(dA[0] + dB[0], dA[1] + dB[1]);
            *(float2*)&Gsm[(mrow + 8) * 36 + nc] = make_float2(dA[2] + dB[2], dA[3] + dB[3]);
        }
        __syncthreads();

        // (5) epilogue: exactly 1 cell per thread (tanh.approx activations)
        {
            float pi = bi_r + Gsm[( 0 + u) * 36 + eb];
            float pf = bf_r + Gsm[( 8 + u) * 36 + eb];
            float po = bo_r + Gsm[(16 + u) * 36 + eb];
            float pc = bc_r + Gsm[(24 + u) * 36 + eb];
            float I = sigf(pi), F = sigf(pf), O = sigf(po), Ct = tanhf_(pc);
            Cr = F * Cr + I * Ct;
            float Hn = O * tanhf_(Cr);
            HnSm[u * 34 + eb] = __float2half_rn(Hn);
            Ysm[u * 36 + eb]  = Hn * wef;
            if (step == SS - 1) {
                g_Hfin[(hbase + u) * BB + bbase + eb] = Hn;
                g_Cbuf[(hbase + u) * BB + bbase + eb] = Cr;
            }
        }
        __syncthreads();

        // (6) pack new H (16B per batch) + Y partial
        if (t < NB) {
            uint32_t p[4];
            #pragma unroll
            for (int uu = 0; uu < 4; uu++) {
                uint32_t lo = (uint32_t)__half_as_ushort(HnSm[(2 * uu)     * 34 + t]);
                uint32_t hi = (uint32_t)__half_as_ushort(HnSm[(2 * uu + 1) * 34 + t]);
                p[uu] = lo | (hi << 16);
            }
            *(uint4*)((unsigned char*)g_Hbuf[(step + 1) & 1]
                      + (size_t)(bbase + t) * 1024 + (size_t)cidx * 16)
                = make_uint4(p[0], p[1], p[2], p[3]);
        } else if (t < 2 * NB) {
            int bb = t - NB;
            float y = 0.f;
            #pragma unroll
            for (int uu = 0; uu < 8; uu++) y += Ysm[uu * 36 + bb];
            g_party[(size_t)cta * (SS * NB) + (size_t)step * NB + bb] = y;
        }

        // (7) group-local 64-CTA barrier (proven pattern)
        __threadfence();
        __syncthreads();
        if (t == 0) {
            atomicAdd(&barp[step], 1u);
            while (atomicAdd(&barp[step], 0u) < (unsigned)NCG) { }
            __threadfence();
        }
        __syncthreads();
    }
}

// ---------------- finalize ----------------------------------------------------
__global__ void __launch_bounds__(NTHR) fin_kernel(float* __restrict__ out, int out_size)
{
    int blk = blockIdx.x, t = threadIdx.x;
    if (blk < SS) {
        if (t < BB) {
            int g = t >> 5, bw = t & 31;
            float y = g_beff[0];
            #pragma unroll
            for (int c = 0; c < NCG; c++)
                y += g_party[(size_t)(g * NCG + c) * (SS * NB) + (size_t)blk * NB + bw];
            int o = blk * BB + t;
            if (o < out_size) out[o] = y;
        }
    } else {
        if (out_size < SS * BB + 2 * HH * BB) return;
        int i = (blk - SS) * NTHR + t;
        if (i < HH * BB) {
            int h = i >> 6, b = i & 63;
            out[SS * BB + b * HH + h] = g_Hfin[i];
        } else {
            int j = i - HH * BB;
            int h = j >> 6, b = j & 63;
            out[SS * BB + HH * BB + b * HH + h] = g_Cbuf[j];
        }
    }
}

// ---------------- launch ------------------------------------------------------
extern "C" void kernel_launch(void* const* d_in, const int* in_sizes, int n_in,
                              void* d_out, int out_size)
{
    const int*   inputs = (const int*)d_in[0];
    const float* H0  = (const float*)d_in[1];
    const float* C0  = (const float*)d_in[2];
    const float* emb = (const float*)d_in[3];
    const float* Wxi = (const float*)d_in[4];
    const float* Whi = (const float*)d_in[5];
    const float* bi  = (const float*)d_in[6];
    const float* Wxf = (const float*)d_in[7];
    const float* Whf = (const float*)d_in[8];
    const float* bf  = (const float*)d_in[9];
    const float* Wxo = (const float*)d_in[10];
    const float* Who = (const float*)d_in[11];
    const float* bo  = (const float*)d_in[12];
    const float* Wxc = (const float*)d_in[13];
    const float* Whc = (const float*)d_in[14];
    const float* bc  = (const float*)d_in[15];
    const float* Whq = (const float*)d_in[16];
    const float* bq  = (const float*)d_in[17];
    const float* dw  = (const float*)d_in[18];
    const float* db  = (const float*)d_in[19];
    float* out = (float*)d_out;

    cudaFuncSetAttribute(rnn_kernel, cudaFuncAttributeMaxDynamicSharedMemorySize, RNN_SMEM);

    init_kernel<<<128, NTHR>>>(H0, C0, Whq, bq, dw, db);
    prep_kernel<<<(NCG * MRR * HH) / NTHR, NTHR>>>(Whi, Whf, Who, Whc);
    prep_x_kernel<<<(NCG * MRR * EE) / NTHR, NTHR>>>(Wxi, Wxf, Wxo, Wxc);
    rnn_kernel<<<NGRP * NCG, NTHR, RNN_SMEM>>>(inputs, emb, bi, bf, bo, bc);
    fin_kernel<<<SS + (2 * HH * BB) / NTHR, NTHR>>>(out, out_size);
}

// round 16
// speedup vs baseline: 1.6677x; 1.0649x over previous
#include <cuda_runtime.h>
#include <cuda_fp16.h>
#include <cstdint>

#define BB   64
#define SS   1024
#define EE   128
#define HH   512
#define NTHR 256
#define NGRP 4         // batch groups
#define NCG  32        // CTAs per group
#define NB   16        // batches per group
#define HPC  16        // h columns per CTA
#define MRR  64        // D rows per CTA = 4 gates x 16 h

// ---- rnn dynamic smem layout (bytes) ----
#define A_BYTES  (MRR * HH * 2)          // 65536 fp16 Wh tile (1024B rows, swizzled)
#define B_BYTES  (NB * HH * 2)           // 16384 fp16 H tile (1024B rows, swizzled)
#define WX_OFF   (A_BYTES + B_BYTES)     // Wx tile [64 m][128 k] fp16, 256B rows
#define WX_BYTES (MRR * EE * 2)          // 16384
#define XS_OFF   (WX_OFF + WX_BYTES)     // X tile [16 b][128 k] fp16, 256B rows
#define XS_BYTES (NB * EE * 2)           // 4096
#define G_OFF    (XS_OFF + XS_BYTES)     // Gsm float[64][18]
#define G_BYTES  (MRR * 18 * 4)          // 4608
#define HN_OFF   (G_OFF + G_BYTES)       // HnSm half[16][18]
#define HN_BYTES (16 * 18 * 2)           // 576
#define YS_OFF   ((HN_OFF + HN_BYTES + 15) & ~15)
#define YS_BYTES (16 * 18 * 4)           // 1152
#define RNN_SMEM (YS_OFF + YS_BYTES)     // ~108KB

// ---------------- module-scope scratch ----------------
__device__ __align__(128) __half        g_Hbuf[2][BB * HH];            // [b][h] fp16
__device__ __align__(128) float         g_Cbuf[HH * BB];               // [h][b]
__device__ __align__(128) float         g_Hfin[HH * BB];               // [h][b]
__device__ __align__(128) float         g_weff[HH];
__device__ __align__(128) float         g_beff[1];
__device__ __align__(128) float         g_party[(size_t)NGRP * NCG * SS * NB];
__device__ __align__(128) unsigned      g_bar[NGRP * SS];              // per-group arrival counters
__device__ __align__(128) unsigned char g_Abuf[(size_t)NCG * A_BYTES];    // Wh images (per cidx)
__device__ __align__(128) unsigned char g_Wxbuf[(size_t)NCG * WX_BYTES];  // Wx images (per cidx)

// fast activations: tanh.approx (1 MUFU)
__device__ __forceinline__ float tanh_fast(float x) {
    float y;
    asm("tanh.approx.f32 %0, %1;" : "=f"(y) : "f"(x));
    return y;
}
__device__ __forceinline__ float sigf(float x)   { return fmaf(0.5f, tanh_fast(0.5f * x), 0.5f); }
__device__ __forceinline__ float tanhf_(float x) { return tanh_fast(x); }

__device__ __forceinline__ uint32_t smem_u32(const void* p) {
    uint32_t a;
    asm("{ .reg .u64 t; cvta.to.shared.u64 t, %1; cvt.u32.u64 %0, t; }" : "=r"(a) : "l"(p));
    return a;
}
__device__ __forceinline__ void ldsm4(uint32_t* r, uint32_t addr) {
    asm volatile("ldmatrix.sync.aligned.m8n8.x4.shared.b16 {%0,%1,%2,%3}, [%4];"
                 : "=r"(r[0]), "=r"(r[1]), "=r"(r[2]), "=r"(r[3]) : "r"(addr));
}
__device__ __forceinline__ void ldsm2(uint32_t* r, uint32_t addr) {
    asm volatile("ldmatrix.sync.aligned.m8n8.x2.shared.b16 {%0,%1}, [%2];"
                 : "=r"(r[0]), "=r"(r[1]) : "r"(addr));
}
__device__ __forceinline__ void mma16816(float* d, const uint32_t* a, const uint32_t* b) {
    asm volatile("mma.sync.aligned.m16n8k16.row.col.f32.f16.f16.f32 "
                 "{%0,%1,%2,%3}, {%4,%5,%6,%7}, {%8,%9}, {%0,%1,%2,%3};"
                 : "+f"(d[0]), "+f"(d[1]), "+f"(d[2]), "+f"(d[3])
                 : "r"(a[0]), "r"(a[1]), "r"(a[2]), "r"(a[3]), "r"(b[0]), "r"(b[1]));
}

// ---------------- init ----------------
__global__ void __launch_bounds__(NTHR) init_kernel(
    const float* __restrict__ H0, const float* __restrict__ C0,
    const float* __restrict__ Whq, const float* __restrict__ bq,
    const float* __restrict__ dw, const float* __restrict__ db)
{
    int t = blockIdx.x * blockDim.x + threadIdx.x;
    if (t < HH * BB) {
        int b = t >> 9, h = t & 511;
        g_Hbuf[0][t]       = __float2half_rn(H0[t]);   // [b][h]
        g_Cbuf[h * BB + b] = C0[t];
    }
    if (t < HH) {
        float a = 0.f;
        #pragma unroll 8
        for (int e = 0; e < EE; e++) a += Whq[t * EE + e] * dw[e];
        g_weff[t] = a;
    }
    if (t == 0) {
        float a = 0.f;
        for (int e = 0; e < EE; e++) a += bq[e] * dw[e];
        g_beff[0] = a + db[0];
    }
    if (t < NGRP * SS) g_bar[t] = 0u;
}

// ---------------- prep: Wh images (1024B rows, swizzled fp16) ----------------
// CTA slice cidx (0..31): row m = g*16+u (u 0..15), value W_hg[k][cidx*16+u]
__global__ void __launch_bounds__(NTHR) prep_kernel(
    const float* __restrict__ Whi, const float* __restrict__ Whf,
    const float* __restrict__ Who, const float* __restrict__ Whc)
{
    int idx = blockIdx.x * blockDim.x + threadIdx.x;   // 32*64*512 = 1M
    int c = idx >> 15;
    int r = idx & 32767;
    int m = r >> 9;
    int k = r & 511;
    int g = m >> 4, u = m & 15;
    const float* W = (g == 0) ? Whi : (g == 1) ? Whf : (g == 2) ? Who : Whc;
    float v = W[(size_t)k * HH + c * HPC + u];
    uint32_t pos = (uint32_t)m * 1024 + (((uint32_t)k * 2) ^ (((uint32_t)m & 7) << 4));
    *(__half*)(g_Abuf + (size_t)c * A_BYTES + pos) = __float2half_rn(v);
}

// ---------------- prep_x: Wx images (256B rows, swizzled fp16) ---------------
__global__ void __launch_bounds__(NTHR) prep_x_kernel(
    const float* __restrict__ Wxi, const float* __restrict__ Wxf,
    const float* __restrict__ Wxo, const float* __restrict__ Wxc)
{
    int idx = blockIdx.x * blockDim.x + threadIdx.x;   // 32*64*128 = 262144
    int c = idx >> 13;
    int r = idx & 8191;
    int m = r >> 7;
    int k = r & 127;
    int g = m >> 4, u = m & 15;
    const float* W = (g == 0) ? Wxi : (g == 1) ? Wxf : (g == 2) ? Wxo : Wxc;
    float v = W[(size_t)k * HH + c * HPC + u];
    uint32_t pos = (uint32_t)m * 256 + (((uint32_t)k * 2) ^ (((uint32_t)m & 7) << 4));
    *(__half*)(g_Wxbuf + (size_t)c * WX_BYTES + pos) = __float2half_rn(v);
}

// ---------------- persistent recurrence: 4 batch groups x 32 CTAs ------------
__global__ void __launch_bounds__(NTHR, 1) rnn_kernel(
    const int* __restrict__ inputs, const float* __restrict__ emb,
    const float* __restrict__ bi,  const float* __restrict__ bf,
    const float* __restrict__ bo,  const float* __restrict__ bc)
{
    extern __shared__ __align__(16) unsigned char sm[];
    float*  Gsm  = (float*)(sm + G_OFF);
    __half* HnSm = (__half*)(sm + HN_OFF);
    float*  Ysm  = (float*)(sm + YS_OFF);
    const uint32_t smb = smem_u32(sm);
    const uint32_t Ab  = smb;
    const uint32_t Bb  = smb + A_BYTES;
    const uint32_t WxB = smb + WX_OFF;
    const uint32_t XsB = smb + XS_OFF;

    const int t = threadIdx.x, lane = t & 31, wid = t >> 5;
    const int cta  = blockIdx.x;
    const int grp  = cta >> 5;            // batch group 0..3
    const int cidx = cta & 31;            // h-slice index within group
    const int hbase = cidx * HPC;
    const int bbase = grp * NB;

    // load prebuilt Wh image (64 KB) + Wx image (16 KB)
    {
        const float4* asrc = (const float4*)(g_Abuf + (size_t)cidx * A_BYTES);
        float4* adst = (float4*)sm;
        #pragma unroll
        for (int j = 0; j < 16; j++)
            adst[j * 256 + t] = __ldg(&asrc[j * 256 + t]);
        const float4* xsrc = (const float4*)(g_Wxbuf + (size_t)cidx * WX_BYTES);
        float4* xdst = (float4*)(sm + WX_OFF);
        #pragma unroll
        for (int j = 0; j < 4; j++)
            xdst[j * 256 + t] = __ldg(&xsrc[j * 256 + t]);
    }

    // GEMM lane mapping: warp slot (mt 0..3, nt 0..1): M 16-rows x N 8-cols
    const int q = lane >> 3, r8 = lane & 7;
    const int mt = wid >> 1;
    const int nt = wid & 1;
    const int arow = mt * 16 + r8 + ((q & 1) << 3);
    const uint32_t acol   = (uint32_t)(q >> 1) * 16;
    const uint32_t aBase  = Ab  + (uint32_t)arow * 1024;
    const uint32_t aBaseX = WxB + (uint32_t)arow * 256;
    const uint32_t axor   = ((uint32_t)arow & 7) << 4;
    const int l16 = lane & 15;
    const int brow = nt * 8 + (l16 & 7);
    const uint32_t bcol   = (uint32_t)(l16 >> 3) * 16;
    const uint32_t bBase  = Bb  + (uint32_t)brow * 1024;
    const uint32_t bBaseX = XsB + (uint32_t)brow * 256;
    const uint32_t bxor   = ((uint32_t)brow & 7) << 4;

    // epilogue role: 1 cell per thread: h = hbase+u (u 0..15), b = bbase+eb (eb 0..15)
    const int u = t >> 4, eb = t & 15;
    float Cr = g_Cbuf[(hbase + u) * BB + bbase + eb];
    const float wef  = g_weff[hbase + u];
    const float bi_r = __ldg(&bi[hbase + u]);
    const float bf_r = __ldg(&bf[hbase + u]);
    const float bo_r = __ldg(&bo[hbase + u]);
    const float bc_r = __ldg(&bc[hbase + u]);
    __syncthreads();

    // X-gather role: 16 rows x 16 parts (8 floats each)
    const int bqi = t >> 4, part = t & 15;
    const int* tok_ptr = inputs + (bbase + bqi) * SS;

    // X pipeline prologue
    float4 xpre[2];
    {
        int tok0 = __ldg(tok_ptr);
        const float4* src = (const float4*)(emb + (size_t)tok0 * EE) + part * 2;
        xpre[0] = __ldg(&src[0]);
        xpre[1] = __ldg(&src[1]);
    }
    int tok1 = __ldg(tok_ptr + 1);

    unsigned* barp = g_bar + grp * SS;

    for (int step = 0; step < SS; step++) {
        // (1) store prefetched X (fp32 regs -> fp16 swizzled smem)
        {
            __half2 h0 = __floats2half2_rn(xpre[0].x, xpre[0].y);
            __half2 h1 = __floats2half2_rn(xpre[0].z, xpre[0].w);
            __half2 h2 = __floats2half2_rn(xpre[1].x, xpre[1].y);
            __half2 h3 = __floats2half2_rn(xpre[1].z, xpre[1].w);
            uint4 u0 = make_uint4(*(uint32_t*)&h0, *(uint32_t*)&h1,
                                  *(uint32_t*)&h2, *(uint32_t*)&h3);
            uint32_t xo = ((uint32_t)bqi & 7) << 4;
            uint32_t c0 = (uint32_t)part * 16;
            *(uint4*)(sm + XS_OFF + bqi * 256 + (c0 ^ xo)) = u0;
        }
        // (2) issue X prefetch for step+1
        if (step + 1 < SS) {
            const float4* src = (const float4*)(emb + (size_t)tok1 * EE) + part * 2;
            xpre[0] = __ldg(&src[0]);
            xpre[1] = __ldg(&src[1]);
            if (step + 2 < SS) tok1 = __ldg(tok_ptr + step + 2);
        }

        // (3) stage this group's H slice [16 b][512 h] fp16 -> Bsm
        {
            const float4* hs = (const float4*)g_Hbuf[step & 1] + bbase * 64;
            #pragma unroll
            for (int j = 0; j < 4; j++) {
                int i16 = j * 256 + t;
                float4 v = __ldcg(&hs[i16]);
                uint32_t b   = (uint32_t)i16 >> 6;
                uint32_t c16 = (uint32_t)i16 & 63;
                *(float4*)(sm + A_BYTES + b * 1024 + ((c16 * 16) ^ ((b & 7) << 4))) = v;
            }
        }
        __syncthreads();

        // (4) GEMM: 8 X k-slices + 32 H k-slices, DUAL accumulators (even/odd)
        float dA[4] = {0.f, 0.f, 0.f, 0.f};
        float dB[4] = {0.f, 0.f, 0.f, 0.f};
        #pragma unroll
        for (int ks = 0; ks < 8; ks += 2) {
            uint32_t a0[4], b0[2], a1[4], b1[2];
            ldsm4(a0, aBaseX + (((uint32_t)ks * 32 + acol) ^ axor));
            ldsm2(b0, bBaseX + (((uint32_t)ks * 32 + bcol) ^ bxor));
            ldsm4(a1, aBaseX + (((uint32_t)(ks + 1) * 32 + acol) ^ axor));
            ldsm2(b1, bBaseX + (((uint32_t)(ks + 1) * 32 + bcol) ^ bxor));
            mma16816(dA, a0, b0);
            mma16816(dB, a1, b1);
        }
        #pragma unroll 8
        for (int ks = 0; ks < 32; ks += 2) {
            uint32_t a0[4], b0[2], a1[4], b1[2];
            ldsm4(a0, aBase + (((uint32_t)ks * 32 + acol) ^ axor));
            ldsm2(b0, bBase + (((uint32_t)ks * 32 + bcol) ^ bxor));
            ldsm4(a1, aBase + (((uint32_t)(ks + 1) * 32 + acol) ^ axor));
            ldsm2(b1, bBase + (((uint32_t)(ks + 1) * 32 + bcol) ^ bxor));
            mma16816(dA, a0, b0);
            mma16816(dB, a1, b1);
        }
        {
            int g4 = lane >> 2, t4 = lane & 3;
            int mrow = mt * 16 + g4, nc = nt * 8 + 2 * t4;
            *(float2*)&Gsm[mrow * 18 + nc]       = make_float2(dA[0] + dB[0], dA[1] + dB[1]);
            *(float2*)&Gsm[(mrow + 8) * 18 + nc] = make_float2(dA[2] + dB[2], dA[3] + dB[3]);
        }
        __syncthreads();

        // (5) epilogue: exactly 1 cell per thread (tanh.approx activations)
        {
            float pi = bi_r + Gsm[( 0 + u) * 18 + eb];
            float pf = bf_r + Gsm[(16 + u) * 18 + eb];
            float po = bo_r + Gsm[(32 + u) * 18 + eb];
            float pc = bc_r + Gsm[(48 + u) * 18 + eb];
            float I = sigf(pi), F = sigf(pf), O = sigf(po), Ct = tanhf_(pc);
            Cr = F * Cr + I * Ct;
            float Hn = O * tanhf_(Cr);
            HnSm[u * 18 + eb] = __float2half_rn(Hn);
            Ysm[u * 18 + eb]  = Hn * wef;
            if (step == SS - 1) {
                g_Hfin[(hbase + u) * BB + bbase + eb] = Hn;
                g_Cbuf[(hbase + u) * BB + bbase + eb] = Cr;
            }
        }
        __syncthreads();

        // (6) pack new H (32B per batch) + Y partial
        if (t < NB) {
            uint32_t p[8];
            #pragma unroll
            for (int uu = 0; uu < 8; uu++) {
                uint32_t lo = (uint32_t)__half_as_ushort(HnSm[(2 * uu)     * 18 + t]);
                uint32_t hi = (uint32_t)__half_as_ushort(HnSm[(2 * uu + 1) * 18 + t]);
                p[uu] = lo | (hi << 16);
            }
            unsigned char* dst = (unsigned char*)g_Hbuf[(step + 1) & 1]
                               + (size_t)(bbase + t) * 1024 + (size_t)cidx * 32;
            *(uint4*)dst        = make_uint4(p[0], p[1], p[2], p[3]);
            *(uint4*)(dst + 16) = make_uint4(p[4], p[5], p[6], p[7]);
        } else if (t < 2 * NB) {
            int bb = t - NB;
            float y = 0.f;
            #pragma unroll
            for (int uu = 0; uu < 16; uu++) y += Ysm[uu * 18 + bb];
            g_party[(size_t)cta * (SS * NB) + (size_t)step * NB + bb] = y;
        }

        // (7) group-local 32-CTA barrier (proven pattern)
        __threadfence();
        __syncthreads();
        if (t == 0) {
            atomicAdd(&barp[step], 1u);
            while (atomicAdd(&barp[step], 0u) < (unsigned)NCG) { }
            __threadfence();
        }
        __syncthreads();
    }
}

// ---------------- finalize ----------------------------------------------------
__global__ void __launch_bounds__(NTHR) fin_kernel(float* __restrict__ out, int out_size)
{
    int blk = blockIdx.x, t = threadIdx.x;
    if (blk < SS) {
        if (t < BB) {
            int g = t >> 4, bw = t & 15;
            float y = g_beff[0];
            #pragma unroll
            for (int c = 0; c < NCG; c++)
                y += g_party[(size_t)(g * NCG + c) * (SS * NB) + (size_t)blk * NB + bw];
            int o = blk * BB + t;
            if (o < out_size) out[o] = y;
        }
    } else {
        if (out_size < SS * BB + 2 * HH * BB) return;
        int i = (blk - SS) * NTHR + t;
        if (i < HH * BB) {
            int h = i >> 6, b = i & 63;
            out[SS * BB + b * HH + h] = g_Hfin[i];
        } else {
            int j = i - HH * BB;
            int h = j >> 6, b = j & 63;
            out[SS * BB + HH * BB + b * HH + h] = g_Cbuf[j];
        }
    }
}

// ---------------- launch ------------------------------------------------------
extern "C" void kernel_launch(void* const* d_in, const int* in_sizes, int n_in,
                              void* d_out, int out_size)
{
    const int*   inputs = (const int*)d_in[0];
    const float* H0  = (const float*)d_in[1];
    const float* C0  = (const float*)d_in[2];
    const float* emb = (const float*)d_in[3];
    const float* Wxi = (const float*)d_in[4];
    const float* Whi = (const float*)d_in[5];
    const float* bi  = (const float*)d_in[6];
    const float* Wxf = (const float*)d_in[7];
    const float* Whf = (const float*)d_in[8];
    const float* bf  = (const float*)d_in[9];
    const float* Wxo = (const float*)d_in[10];
    const float* Who = (const float*)d_in[11];
    const float* bo  = (const float*)d_in[12];
    const float* Wxc = (const float*)d_in[13];
    const float* Whc = (const float*)d_in[14];
    const float* bc  = (const float*)d_in[15];
    const float* Whq = (const float*)d_in[16];
    const float* bq  = (const float*)d_in[17];
    const float* dw  = (const float*)d_in[18];
    const float* db  = (const float*)d_in[19];
    float* out = (float*)d_out;

    cudaFuncSetAttribute(rnn_kernel, cudaFuncAttributeMaxDynamicSharedMemorySize, RNN_SMEM);

    init_kernel<<<128, NTHR>>>(H0, C0, Whq, bq, dw, db);
    prep_kernel<<<(NCG * MRR * HH) / NTHR, NTHR>>>(Whi, Whf, Who, Whc);
    prep_x_kernel<<<(NCG * MRR * EE) / NTHR, NTHR>>>(Wxi, Wxf, Wxo, Wxc);
    rnn_kernel<<<NGRP * NCG, NTHR, RNN_SMEM>>>(inputs, emb, bi, bf, bo, bc);
    fin_kernel<<<SS + (2 * HH * BB) / NTHR, NTHR>>>(out, out_size);
}